// round 15
// baseline (speedup 1.0000x reference)
#include <cuda_runtime.h>
#include <cuda_bf16.h>
#include <cuda_fp16.h>
#include <math.h>
#include <stdint.h>

#define BB   4
#define NN_  1024
#define KD_  512
#define HH   8
#define MEMN 4096
#define BWN  1024
#define RQ   (BB*HH*NN_)
#define RB   (BB*NN_)

typedef __nv_bfloat16 bf16;

// ---------------- scratch ----------------
__device__ float  g_A  [(size_t)BWN * KD_];          // wk@WgTop + bg
__device__ float  g_BV [(size_t)BWN * KD_];          // V0[idx]@WgBot
__device__ float  g_rsum[RQ];                        // softmax row sums
__device__ int    g_idx[BWN];
__device__ unsigned long long g_pk[BWN];             // packed (val,idx) argmax
__device__ __half g_QI16[(size_t)RB * KD_];
__device__ __half g_Q16[(size_t)RQ * KD_];
__device__ __half g_P16[(size_t)RQ * MEMN];          // exp(scores) fp16
__device__ __half g_RV16[(size_t)RB * (HH*KD_)];
__device__ __half g_MK16[(size_t)MEMN * KD_];
__device__ __half g_MVT16[(size_t)KD_ * MEMN];
__device__ __half g_WqT16[(size_t)(HH*KD_) * KD_];
__device__ __half g_WvpT16[(size_t)KD_ * (HH*KD_)];
__device__ bf16 g_KNh[(size_t)BWN * KD_],  g_KNl[(size_t)BWN * KD_];
__device__ bf16 g_MNh[(size_t)MEMN * KD_], g_MNl[(size_t)MEMN * KD_];
__device__ bf16 g_WgTh[(size_t)KD_ * KD_], g_WgTl[(size_t)KD_ * KD_];
__device__ bf16 g_WgBh[(size_t)KD_ * KD_], g_WgBl[(size_t)KD_ * KD_];
__device__ bf16 g_WB16[(size_t)KD_ * KD_];           // WgBot row-major bf16 (chain matvec)
__device__ bf16 g_GAh[(size_t)2*BWN * KD_], g_GAl[(size_t)2*BWN * KD_];  // [wk rows | V0[idx] rows]

// ---------------- helpers ----------------
__device__ __forceinline__ uint32_t smem_to_u32(const void* p) {
    uint32_t a;
    asm("{ .reg .u64 t; cvta.to.shared.u64 t, %1; cvt.u32.u64 %0, t; }" : "=r"(a) : "l"(p));
    return a;
}
__device__ __forceinline__ void ldsm4(uint32_t* r, uint32_t addr) {
    asm volatile("ldmatrix.sync.aligned.m8n8.x4.shared.b16 {%0,%1,%2,%3}, [%4];"
                 : "=r"(r[0]), "=r"(r[1]), "=r"(r[2]), "=r"(r[3]) : "r"(addr));
}
__device__ __forceinline__ void mma_bf(float* c, const uint32_t* a, const uint32_t* b) {
    asm volatile(
        "mma.sync.aligned.m16n8k16.row.col.f32.bf16.bf16.f32 "
        "{%0,%1,%2,%3}, {%4,%5,%6,%7}, {%8,%9}, {%0,%1,%2,%3};"
        : "+f"(c[0]), "+f"(c[1]), "+f"(c[2]), "+f"(c[3])
        : "r"(a[0]), "r"(a[1]), "r"(a[2]), "r"(a[3]), "r"(b[0]), "r"(b[1]));
}
__device__ __forceinline__ void mma_fp(float* c, const uint32_t* a, const uint32_t* b) {
    asm volatile(
        "mma.sync.aligned.m16n8k16.row.col.f32.f16.f16.f32 "
        "{%0,%1,%2,%3}, {%4,%5,%6,%7}, {%8,%9}, {%0,%1,%2,%3};"
        : "+f"(c[0]), "+f"(c[1]), "+f"(c[2]), "+f"(c[3])
        : "r"(a[0]), "r"(a[1]), "r"(a[2]), "r"(a[3]), "r"(b[0]), "r"(b[1]));
}
__device__ __forceinline__ void cp16(uint32_t dst, const void* src) {
    asm volatile("cp.async.cg.shared.global [%0], [%1], 16;" :: "r"(dst), "l"(src));
}
#define CP_COMMIT() asm volatile("cp.async.commit_group;" ::: "memory")
#define CP_WAIT1()  asm volatile("cp.async.wait_group 1;" ::: "memory")

__device__ __forceinline__ void splitpack(float x, float y, uint32_t& h, uint32_t& l) {
    bf16 hx = __float2bfloat16(x), hy = __float2bfloat16(y);
    float rx = x - __bfloat162float(hx), ry = y - __bfloat162float(hy);
    bf16 lx = __float2bfloat16(rx), ly = __float2bfloat16(ry);
    h = (uint32_t)__bfloat16_as_ushort(hx) | ((uint32_t)__bfloat16_as_ushort(hy) << 16);
    l = (uint32_t)__bfloat16_as_ushort(lx) | ((uint32_t)__bfloat16_as_ushort(ly) << 16);
}
__device__ __forceinline__ unsigned long long packmax(float v, int col) {
    uint32_t b = __float_as_uint(v);
    b = (b & 0x80000000u) ? ~b : (b | 0x80000000u);
    return ((unsigned long long)b << 32) | (unsigned long long)(0xFFFFFFFFu - (uint32_t)col);
}
__device__ __forceinline__ float2 bf2_to_f2(uint32_t u) {
    float2 r;
    r.x = __uint_as_float(u << 16);
    r.y = __uint_as_float(u & 0xFFFF0000u);
    return r;
}

#define TN 128
#define ROWB 144    // KC=32 bf16 hi|lo row
#define ROWB1 272   // KC=128 fp16 row
#define KC3 32

template<int MODE>
__device__ __forceinline__ size_t dst_of(int r, int c, int N) {
    if (MODE == 0 || MODE == 5) return (size_t)r * N + c;
    if (MODE == 1) {
        const int b_ = r >> 10, n_ = r & 1023, h_ = c >> 9, d_ = c & 511;
        return ((size_t)((b_ * 8 + h_) * 1024 + n_) << 9) + d_;
    }
    const int b_ = r >> 13, h_ = (r >> 10) & 7, n_ = r & 1023;
    return ((size_t)(b_ * 1024 + n_) << 12) + ((size_t)h_ << 9) + c;
}

// ================= 3-term split-bf16 GEMM, TM=256 (MODE 3: fused row-argmax) =================
#define TM3 256
#define STAGE3 ((TM3 + TN) * ROWB)
#define DYN3 (2 * STAGE3)

template<int MODE>
__global__ void __launch_bounds__(256, 1)
bgemm3(const bf16* __restrict__ Ah, const bf16* __restrict__ Al,
       const bf16* __restrict__ Bh, const bf16* __restrict__ Bl,
       const float* __restrict__ bias, float* __restrict__ C,
       unsigned long long* __restrict__ Packed,
       int M, int N, int K, float scale)
{
    extern __shared__ char sm[];
    const uint32_t smem_u = smem_to_u32(sm);
    const int tid = threadIdx.x;
    const int lane = tid & 31, wid = tid >> 5;
    const int bm = blockIdx.y * TM3, bn = blockIdx.x * TN;
    const int wm = (wid >> 1) * 64, wn = (wid & 1) * 64;

    float acc[4][8][4];
#pragma unroll
    for (int i = 0; i < 4; i++)
#pragma unroll
        for (int j = 0; j < 8; j++)
#pragma unroll
            for (int k = 0; k < 4; k++) acc[i][j][k] = 0.0f;

    const int NC = K / KC3;

    auto load_chunk = [&](int c, int st) {
        const int k0 = c * KC3;
        const uint32_t sb = smem_u + st * STAGE3;
#pragma unroll
        for (int u = 0; u < 3; u++) {
            const int unit = tid + u * 256;
            const int r = (unit & 511) >> 1, pl = unit & 1;
            const bf16* src;
            uint32_t dst;
            if (unit < 512) {
                src = (pl ? Al : Ah) + (size_t)(bm + r) * K + k0;
                dst = sb + r * ROWB + pl * 64;
            } else {
                src = (pl ? Bl : Bh) + (size_t)(bn + r) * K + k0;
                dst = sb + (TM3 + r) * ROWB + pl * 64;
            }
#pragma unroll
            for (int i = 0; i < 4; i++) cp16(dst + i * 16, src + i * 8);
        }
    };

    load_chunk(0, 0); CP_COMMIT();
    load_chunk(1, 1); CP_COMMIT();

    const int mr = lane & 7, msel = lane >> 3;
    const int aro = ((msel & 1) << 3) + mr;
    const int aco = (msel >> 1) << 3;
    const int bro = ((msel >> 1) << 3) + mr;
    const int bco = (msel & 1) << 3;

    for (int c = 0; c < NC; c++) {
        CP_WAIT1();
        __syncthreads();
        const uint32_t base = smem_u + (c & 1) * STAGE3;
#pragma unroll
        for (int ks = 0; ks < 2; ks++) {
            uint32_t ah[4][4], al[4][4], bh[8][2], bl[8][2];
            const int colA = (ks * 16 + aco) * 2;
            const int colB = (ks * 16 + bco) * 2;
#pragma unroll
            for (int mi = 0; mi < 4; mi++) {
                const uint32_t ad = base + (wm + mi * 16 + aro) * ROWB + colA;
                ldsm4(ah[mi], ad);
                ldsm4(al[mi], ad + 64);
            }
#pragma unroll
            for (int g = 0; g < 4; g++) {
                const uint32_t bd = base + (TM3 + wn + g * 16 + bro) * ROWB + colB;
                uint32_t t[4];
                ldsm4(t, bd);
                bh[2*g][0] = t[0]; bh[2*g][1] = t[1];
                bh[2*g+1][0] = t[2]; bh[2*g+1][1] = t[3];
                ldsm4(t, bd + 64);
                bl[2*g][0] = t[0]; bl[2*g][1] = t[1];
                bl[2*g+1][0] = t[2]; bl[2*g+1][1] = t[3];
            }
#pragma unroll
            for (int mi = 0; mi < 4; mi++)
#pragma unroll
                for (int nb = 0; nb < 8; nb++) {
                    mma_bf(acc[mi][nb], ah[mi], bh[nb]);
                    mma_bf(acc[mi][nb], ah[mi], bl[nb]);
                    mma_bf(acc[mi][nb], al[mi], bh[nb]);
                }
        }
        __syncthreads();
        if (c + 2 < NC) load_chunk(c + 2, c & 1);
        CP_COMMIT();
    }

    const int group = lane >> 2, tig = lane & 3;
    if (MODE == 3) {
#pragma unroll
        for (int mi = 0; mi < 4; mi++) {
#pragma unroll
            for (int half = 0; half < 2; half++) {
                const int row = bm + wm + mi * 16 + group + half * 8;
                float bv = -1e30f; int bc = 0;
#pragma unroll
                for (int nb = 0; nb < 8; nb++) {
                    const int col = bn + wn + nb * 8 + tig * 2;
                    const float v0 = acc[mi][nb][half * 2 + 0];
                    const float v1 = acc[mi][nb][half * 2 + 1];
                    if (v0 > bv) { bv = v0; bc = col; }
                    if (v1 > bv) { bv = v1; bc = col + 1; }
                }
#pragma unroll
                for (int m = 1; m <= 2; m <<= 1) {
                    float ov = __shfl_xor_sync(0xffffffffu, bv, m);
                    int   oc = __shfl_xor_sync(0xffffffffu, bc, m);
                    if (ov > bv || (ov == bv && oc < bc)) { bv = ov; bc = oc; }
                }
                if (tig == 0) atomicMax(Packed + row, packmax(bv, bc));
            }
        }
    } else {
#pragma unroll
        for (int mi = 0; mi < 4; mi++) {
            const int r_lo = bm + wm + mi * 16 + group;
#pragma unroll
            for (int nb = 0; nb < 8; nb++) {
                const int col = bn + wn + nb * 8 + tig * 2;
                float b0 = 0.0f, b1 = 0.0f;
                if (bias) { b0 = bias[col]; b1 = bias[col + 1]; }
                *reinterpret_cast<float2*>(&C[(size_t)r_lo * N + col]) =
                    make_float2((acc[mi][nb][0] + b0) * scale, (acc[mi][nb][1] + b1) * scale);
                *reinterpret_cast<float2*>(&C[(size_t)(r_lo + 8) * N + col]) =
                    make_float2((acc[mi][nb][2] + b0) * scale, (acc[mi][nb][3] + b1) * scale);
            }
        }
    }
}

// ====== small-tile 3-term gate GEMM: M=2048 (rows<1024: WgT+bias->outA; else WgB->outBV) ======
#define TMS 64
#define TNS 64
#define STAGES ((TMS + TNS) * ROWB)
#define DYNS (2 * STAGES)

__global__ void __launch_bounds__(128, 1)
bgemm3s(const bf16* __restrict__ Ah, const bf16* __restrict__ Al,
        const bf16* __restrict__ B1h, const bf16* __restrict__ B1l,
        const bf16* __restrict__ B2h, const bf16* __restrict__ B2l,
        const float* __restrict__ bias, float* __restrict__ outA, float* __restrict__ outBV)
{
    constexpr int K = KD_, N = KD_;
    extern __shared__ char sm[];
    const uint32_t smem_u = smem_to_u32(sm);
    const int tid = threadIdx.x;
    const int lane = tid & 31, wid = tid >> 5;
    const int bm = blockIdx.y * TMS, bn = blockIdx.x * TNS;
    const bool second = bm >= BWN;
    const bf16* Bh = second ? B2h : B1h;
    const bf16* Bl = second ? B2l : B1l;
    float* out = second ? outBV : outA;
    const int rowbase = second ? bm - BWN : bm;
    const int wm = (wid >> 1) * 32, wn = (wid & 1) * 32;

    float acc[2][4][4];
#pragma unroll
    for (int i = 0; i < 2; i++)
#pragma unroll
        for (int j = 0; j < 4; j++)
#pragma unroll
            for (int k = 0; k < 4; k++) acc[i][j][k] = 0.0f;

    const int NC = K / KC3;

    auto load_chunk = [&](int c, int st) {
        const int k0 = c * KC3;
        const uint32_t sb = smem_u + st * STAGES;
#pragma unroll
        for (int u = 0; u < 2; u++) {
            const int unit = tid + u * 128;
            const int r = (unit & 127) >> 1, pl = unit & 1;
            const bf16* src;
            uint32_t dst;
            if (unit < 128) {
                src = (pl ? Al : Ah) + (size_t)(bm + r) * K + k0;
                dst = sb + r * ROWB + pl * 64;
            } else {
                src = (pl ? Bl : Bh) + (size_t)(bn + r) * K + k0;
                dst = sb + (TMS + r) * ROWB + pl * 64;
            }
#pragma unroll
            for (int i = 0; i < 4; i++) cp16(dst + i * 16, src + i * 8);
        }
    };

    load_chunk(0, 0); CP_COMMIT();
    load_chunk(1, 1); CP_COMMIT();

    const int mr = lane & 7, msel = lane >> 3;
    const int aro = ((msel & 1) << 3) + mr;
    const int aco = (msel >> 1) << 3;
    const int bro = ((msel >> 1) << 3) + mr;
    const int bco = (msel & 1) << 3;

    for (int c = 0; c < NC; c++) {
        CP_WAIT1();
        __syncthreads();
        const uint32_t base = smem_u + (c & 1) * STAGES;
#pragma unroll
        for (int ks = 0; ks < 2; ks++) {
            uint32_t ah[2][4], al[2][4], bh[4][2], bl[4][2];
            const int colA = (ks * 16 + aco) * 2;
            const int colB = (ks * 16 + bco) * 2;
#pragma unroll
            for (int mi = 0; mi < 2; mi++) {
                const uint32_t ad = base + (wm + mi * 16 + aro) * ROWB + colA;
                ldsm4(ah[mi], ad);
                ldsm4(al[mi], ad + 64);
            }
#pragma unroll
            for (int g = 0; g < 2; g++) {
                const uint32_t bd = base + (TMS + wn + g * 16 + bro) * ROWB + colB;
                uint32_t t[4];
                ldsm4(t, bd);
                bh[2*g][0] = t[0]; bh[2*g][1] = t[1];
                bh[2*g+1][0] = t[2]; bh[2*g+1][1] = t[3];
                ldsm4(t, bd + 64);
                bl[2*g][0] = t[0]; bl[2*g][1] = t[1];
                bl[2*g+1][0] = t[2]; bl[2*g+1][1] = t[3];
            }
#pragma unroll
            for (int mi = 0; mi < 2; mi++)
#pragma unroll
                for (int nb = 0; nb < 4; nb++) {
                    mma_bf(acc[mi][nb], ah[mi], bh[nb]);
                    mma_bf(acc[mi][nb], ah[mi], bl[nb]);
                    mma_bf(acc[mi][nb], al[mi], bh[nb]);
                }
        }
        __syncthreads();
        if (c + 2 < NC) load_chunk(c + 2, c & 1);
        CP_COMMIT();
    }

    const int group = lane >> 2, tig = lane & 3;
#pragma unroll
    for (int mi = 0; mi < 2; mi++) {
        const int r_lo = rowbase + wm + mi * 16 + group;
#pragma unroll
        for (int nb = 0; nb < 4; nb++) {
            const int col = bn + wn + nb * 8 + tig * 2;
            float b0 = 0.0f, b1 = 0.0f;
            if (!second) { b0 = bias[col]; b1 = bias[col + 1]; }
            *reinterpret_cast<float2*>(&out[(size_t)r_lo * N + col]) =
                make_float2(acc[mi][nb][0] + b0, acc[mi][nb][1] + b1);
            *reinterpret_cast<float2*>(&out[(size_t)(r_lo + 8) * N + col]) =
                make_float2(acc[mi][nb][2] + b0, acc[mi][nb][3] + b1);
        }
    }
}

// ================= single-term fp16 GEMM (KC=128), TM = WM*64 =================
#define KC1 128

template<int MODE, int WM>
__global__ void __launch_bounds__(WM*64, 1)
hgemm1(const __half* __restrict__ A, const __half* __restrict__ B,
       const float* __restrict__ bias,
       float* __restrict__ C, __half* __restrict__ C16,
       const float* __restrict__ rsum, float* __restrict__ rsumo,
       int M, int N, int K, float scale)
{
    constexpr int TMv = WM * 64;
    constexpr int NT  = WM * 64;
    constexpr int STAGE = (TMv + TN) * ROWB1;
    extern __shared__ char sm[];
    const uint32_t smem_u = smem_to_u32(sm);
    const int tid = threadIdx.x;
    const int lane = tid & 31, wid = tid >> 5;
    const int bm = blockIdx.y * TMv, bn = blockIdx.x * TN;
    const int wm = (wid >> 1) * 64, wn = (wid & 1) * 64;

    float acc[4][8][4];
#pragma unroll
    for (int i = 0; i < 4; i++)
#pragma unroll
        for (int j = 0; j < 8; j++)
#pragma unroll
            for (int k = 0; k < 4; k++) acc[i][j][k] = 0.0f;

    const int NC = K / KC1;

    auto load_chunk = [&](int c, int st) {
        const int k0 = c * KC1;
        const uint32_t sb = smem_u + st * STAGE;
#pragma unroll
        for (int u = tid; u < (TMv + TN) * 16; u += NT) {
            const int r = u >> 4, seg = u & 15;
            const __half* src = (r < TMv)
                ? A + (size_t)(bm + r) * K + k0 + seg * 8
                : B + (size_t)(bn + (r - TMv)) * K + k0 + seg * 8;
            cp16(sb + r * ROWB1 + seg * 16, src);
        }
    };

    load_chunk(0, 0); CP_COMMIT();
    load_chunk(1, 1); CP_COMMIT();

    const int mr = lane & 7, msel = lane >> 3;
    const int aro = ((msel & 1) << 3) + mr;
    const int aco = (msel >> 1) << 3;
    const int bro = ((msel >> 1) << 3) + mr;
    const int bco = (msel & 1) << 3;

    for (int c = 0; c < NC; c++) {
        CP_WAIT1();
        __syncthreads();
        const uint32_t base = smem_u + (c & 1) * STAGE;
#pragma unroll
        for (int ks = 0; ks < 8; ks++) {
            uint32_t ah[4][4], bh[8][2];
            const int colA = (ks * 16 + aco) * 2;
            const int colB = (ks * 16 + bco) * 2;
#pragma unroll
            for (int mi = 0; mi < 4; mi++)
                ldsm4(ah[mi], base + (wm + mi * 16 + aro) * ROWB1 + colA);
#pragma unroll
            for (int g = 0; g < 4; g++) {
                uint32_t t[4];
                ldsm4(t, base + (TMv + wn + g * 16 + bro) * ROWB1 + colB);
                bh[2*g][0] = t[0]; bh[2*g][1] = t[1];
                bh[2*g+1][0] = t[2]; bh[2*g+1][1] = t[3];
            }
#pragma unroll
            for (int mi = 0; mi < 4; mi++)
#pragma unroll
                for (int nb = 0; nb < 8; nb++)
                    mma_fp(acc[mi][nb], ah[mi], bh[nb]);
        }
        __syncthreads();
        if (c + 2 < NC) load_chunk(c + 2, c & 1);
        CP_COMMIT();
    }

    const int group = lane >> 2, tig = lane & 3;
    if (MODE == 5) {
#pragma unroll
        for (int mi = 0; mi < 4; mi++) {
            const int r_lo = bm + wm + mi * 16 + group;
            float rs0 = 0.0f, rs1 = 0.0f;
#pragma unroll
            for (int nb = 0; nb < 8; nb++) {
                const int col = bn + wn + nb * 8 + tig * 2;
                float e00 = __expf(acc[mi][nb][0]);
                float e01 = __expf(acc[mi][nb][1]);
                float e10 = __expf(acc[mi][nb][2]);
                float e11 = __expf(acc[mi][nb][3]);
                rs0 += e00 + e01;
                rs1 += e10 + e11;
                *reinterpret_cast<__half2*>(&C16[(size_t)r_lo * N + col]) = __floats2half2_rn(e00, e01);
                *reinterpret_cast<__half2*>(&C16[(size_t)(r_lo + 8) * N + col]) = __floats2half2_rn(e10, e11);
            }
            rs0 += __shfl_xor_sync(0xffffffffu, rs0, 1);
            rs0 += __shfl_xor_sync(0xffffffffu, rs0, 2);
            rs1 += __shfl_xor_sync(0xffffffffu, rs1, 1);
            rs1 += __shfl_xor_sync(0xffffffffu, rs1, 2);
            if (tig == 0) {
                atomicAdd(rsumo + r_lo, rs0);
                atomicAdd(rsumo + r_lo + 8, rs1);
            }
        }
    } else {
#pragma unroll
        for (int mi = 0; mi < 4; mi++) {
            const int r_lo = bm + wm + mi * 16 + group;
            float s0 = scale, s1 = scale;
            if (MODE == 2) {
                s0 = scale / rsum[r_lo];
                s1 = scale / rsum[r_lo + 8];
            }
#pragma unroll
            for (int nb = 0; nb < 8; nb++) {
                const int col = bn + wn + nb * 8 + tig * 2;
                float b0 = 0.0f, b1 = 0.0f;
                if (bias) { b0 = bias[col]; b1 = bias[col + 1]; }
                float v00 = (acc[mi][nb][0] + b0) * s0;
                float v01 = (acc[mi][nb][1] + b1) * s0;
                float v10 = (acc[mi][nb][2] + b0) * s1;
                float v11 = (acc[mi][nb][3] + b1) * s1;
                if (MODE == 0) {
                    *reinterpret_cast<float2*>(&C[dst_of<0>(r_lo,     col, N)]) = make_float2(v00, v01);
                    *reinterpret_cast<float2*>(&C[dst_of<0>(r_lo + 8, col, N)]) = make_float2(v10, v11);
                } else {
                    *reinterpret_cast<__half2*>(&C16[dst_of<MODE>(r_lo,     col, N)]) = __floats2half2_rn(v00, v01);
                    *reinterpret_cast<__half2*>(&C16[dst_of<MODE>(r_lo + 8, col, N)]) = __floats2half2_rn(v10, v11);
                }
            }
        }
    }
}

// ---------------- prep / small kernels ----------------
__global__ void __launch_bounds__(256) transpose_split(const float* __restrict__ in,
                                                       bf16* __restrict__ oh, bf16* __restrict__ ol,
                                                       bf16* __restrict__ raw16,
                                                       int R, int C)
{
    __shared__ float t[32][33];
    const int c0 = blockIdx.x * 32, r0 = blockIdx.y * 32;
    const int x = threadIdx.x & 31, y = threadIdx.x >> 5;
#pragma unroll
    for (int i = 0; i < 32; i += 8) {
        float v = in[(size_t)(r0 + y + i) * C + c0 + x];
        t[y + i][x] = v;
        if (raw16) raw16[(size_t)(r0 + y + i) * C + c0 + x] = __float2bfloat16(v);
    }
    __syncthreads();
#pragma unroll
    for (int i = 0; i < 32; i += 8) {
        float v = t[x][y + i];
        bf16 h = __float2bfloat16(v);
        bf16 l = __float2bfloat16(v - __bfloat162float(h));
        const size_t d = (size_t)(c0 + y + i) * R + r0 + x;
        oh[d] = h; ol[d] = l;
    }
}

__global__ void __launch_bounds__(256) transpose_half(const float* __restrict__ in,
                                                      __half* __restrict__ out, int R, int C)
{
    __shared__ float t[32][33];
    const int c0 = blockIdx.x * 32, r0 = blockIdx.y * 32;
    const int x = threadIdx.x & 31, y = threadIdx.x >> 5;
#pragma unroll
    for (int i = 0; i < 32; i += 8) t[y + i][x] = in[(size_t)(r0 + y + i) * C + c0 + x];
    __syncthreads();
#pragma unroll
    for (int i = 0; i < 32; i += 8)
        out[(size_t)(c0 + y + i) * R + r0 + x] = __float2half(t[x][y + i]);
}

// fused main-stream prologue: blocks [0,2048) cvt queries->fp16;
// blocks [2048,4096) transpose Wq [512,4096] -> WqT fp16 [4096,512]
#define CVT_BLKS (RB*KD_/512)   // 2048
__global__ void __launch_bounds__(256) prologue_fused(const float* __restrict__ queries,
                                                      __half* __restrict__ qout,
                                                      const float* __restrict__ Wq,
                                                      __half* __restrict__ WqT)
{
    const int bid = blockIdx.x;
    if (bid < CVT_BLKS) {
        const int i = (bid * 256 + threadIdx.x) * 2;
        float2 v = *reinterpret_cast<const float2*>(&queries[i]);
        *reinterpret_cast<__half2*>(&qout[i]) = __floats2half2_rn(v.x, v.y);
    } else {
        __shared__ float t[32][33];
        const int tb = bid - CVT_BLKS;          // 0..2047
        const int bx = tb & 127, by = tb >> 7;  // grid (128, 16)
        const int c0 = bx * 32, r0 = by * 32;   // C = HH*KD_ = 4096, R = KD_ = 512
        const int x = threadIdx.x & 31, y = threadIdx.x >> 5;
#pragma unroll
        for (int i = 0; i < 32; i += 8) t[y + i][x] = Wq[(size_t)(r0 + y + i) * (HH*KD_) + c0 + x];
        __syncthreads();
#pragma unroll
        for (int i = 0; i < 32; i += 8)
            WqT[(size_t)(c0 + y + i) * KD_ + r0 + x] = __float2half(t[x][y + i]);
    }
}

// mem_keys: one read -> normalized bf16 planes + raw fp16
__global__ void __launch_bounds__(256) mem_prep(const float* __restrict__ X,
                                                bf16* __restrict__ oh, bf16* __restrict__ ol,
                                                __half* __restrict__ o16)
{
    __shared__ float red[256];
    const int r = blockIdx.x, tid = threadIdx.x;
    const float* p = X + (size_t)r * KD_;
    float ss = 0.0f;
    for (int i = tid; i < KD_; i += 256) { float v = p[i]; ss += v * v; }
    red[tid] = ss; __syncthreads();
    for (int s = 128; s > 0; s >>= 1) { if (tid < s) red[tid] += red[tid + s]; __syncthreads(); }
    const float inv = 1.0f / fmaxf(sqrtf(red[0]), 1e-8f);
    const int i = tid * 2;
    float2 v = *reinterpret_cast<const float2*>(&p[i]);
    uint32_t h, l;
    splitpack(v.x * inv, v.y * inv, h, l);
    *reinterpret_cast<uint32_t*>(&oh[(size_t)r * KD_ + i]) = h;
    *reinterpret_cast<uint32_t*>(&ol[(size_t)r * KD_ + i]) = l;
    *reinterpret_cast<__half2*>(&o16[(size_t)r * KD_ + i]) = __floats2half2_rn(v.x, v.y);
}

// write_keys: one read -> normalized planes (sim) + raw planes (gate top half)
__global__ void __launch_bounds__(256) wk_prep(const float* __restrict__ X,
                                               bf16* __restrict__ nh, bf16* __restrict__ nl,
                                               bf16* __restrict__ gh, bf16* __restrict__ gl)
{
    __shared__ float red[256];
    const int r = blockIdx.x, tid = threadIdx.x;
    const float* p = X + (size_t)r * KD_;
    float ss = 0.0f;
    for (int i = tid; i < KD_; i += 256) { float v = p[i]; ss += v * v; }
    red[tid] = ss; __syncthreads();
    for (int s = 128; s > 0; s >>= 1) { if (tid < s) red[tid] += red[tid + s]; __syncthreads(); }
    const float inv = 1.0f / fmaxf(sqrtf(red[0]), 1e-8f);
    const int i = tid * 2;
    float2 v = *reinterpret_cast<const float2*>(&p[i]);
    uint32_t h, l;
    splitpack(v.x * inv, v.y * inv, h, l);
    *reinterpret_cast<uint32_t*>(&nh[(size_t)r * KD_ + i]) = h;
    *reinterpret_cast<uint32_t*>(&nl[(size_t)r * KD_ + i]) = l;
    splitpack(v.x, v.y, h, l);
    *reinterpret_cast<uint32_t*>(&gh[(size_t)r * KD_ + i]) = h;
    *reinterpret_cast<uint32_t*>(&gl[(size_t)r * KD_ + i]) = l;
}

__global__ void __launch_bounds__(256) gather_unpack(const unsigned long long* __restrict__ pk,
                                                     const float* __restrict__ mv,
                                                     int* __restrict__ idx,
                                                     bf16* __restrict__ gh, bf16* __restrict__ gl)
{
    const int t = blockIdx.x, tid = threadIdx.x;
    const unsigned long long v = pk[t];
    const int col = (int)(0xFFFFFFFFu - (uint32_t)(v & 0xFFFFFFFFu));
    if (tid == 0) idx[t] = col;
    const float* src = mv + (size_t)col * KD_;
    const int i = tid * 2;
    uint32_t h, l;
    splitpack(src[i], src[i + 1], h, l);
    *reinterpret_cast<uint32_t*>(&gh[(size_t)(BWN + t) * KD_ + i]) = h;
    *reinterpret_cast<uint32_t*>(&gl[(size_t)(BWN + t) * KD_ + i]) = l;
}

__global__ void __launch_bounds__(256) chain_update(
    const float* __restrict__ wk, const float* __restrict__ wv,
    const uint32_t* __restrict__ WB,
    const float* __restrict__ Aw,
    const float* __restrict__ BV,
    const int*   __restrict__ idx,
    const float* __restrict__ mk, const float* __restrict__ mv,
    float* __restrict__ outK, float* __restrict__ outV)
{
    __shared__ float sK[KD_], sV[KD_];
    __shared__ int   list[BWN];
    __shared__ int   cnt;
    const int s = blockIdx.x, tid = threadIdx.x;
    if (tid == 0) cnt = 0;
    __syncthreads();
    for (int t = tid; t < BWN; t += 256)
        if (idx[t] == s) { int p = atomicAdd(&cnt, 1); list[p] = t; }
    __syncthreads();
    const int n = cnt;
    if (n == 0) return;
    if (tid == 0) {
        for (int i = 1; i < n; i++) {
            int v = list[i], j = i - 1;
            while (j >= 0 && list[j] > v) { list[j + 1] = list[j]; j--; }
            list[j + 1] = v;
        }
    }
    for (int i = tid; i < KD_; i += 256) {
        sK[i] = mk[(size_t)s * KD_ + i];
        sV[i] = mv[(size_t)s * KD_ + i];
    }
    __syncthreads();
    const int j0 = tid * 2;
    for (int e = 0; e < n; e++) {
        const int t = list[e];
        float a0, a1;
        {
            float2 aw = *reinterpret_cast<const float2*>(&Aw[(size_t)t * KD_ + j0]);
            a0 = aw.x; a1 = aw.y;
        }
        if (e == 0) {
            float2 bv = *reinterpret_cast<const float2*>(&BV[(size_t)t * KD_ + j0]);
            a0 += bv.x; a1 += bv.y;
        } else {
#pragma unroll 8
            for (int r = 0; r < KD_; r++) {
                const float v = sV[r];
                float2 w = bf2_to_f2(WB[r * 256 + tid]);
                a0 += v * w.x;
                a1 += v * w.y;
            }
        }
        const float g0 = 1.0f / (1.0f + expf(-a0));
        const float g1 = 1.0f / (1.0f + expf(-a1));
        __syncthreads();
        float2 k2 = *reinterpret_cast<const float2*>(&wk[(size_t)t * KD_ + j0]);
        float2 v2 = *reinterpret_cast<const float2*>(&wv[(size_t)t * KD_ + j0]);
        sK[j0]     = g0 * k2.x + (1.0f - g0) * sK[j0];
        sK[j0 + 1] = g1 * k2.y + (1.0f - g1) * sK[j0 + 1];
        sV[j0]     = g0 * v2.x + (1.0f - g0) * sV[j0];
        sV[j0 + 1] = g1 * v2.y + (1.0f - g1) * sV[j0 + 1];
        __syncthreads();
    }
    for (int i = tid; i < KD_; i += 256) {
        outK[(size_t)s * KD_ + i] = sK[i];
        outV[(size_t)s * KD_ + i] = sV[i];
    }
}

// ---------------- launcher ----------------
extern "C" void kernel_launch(void* const* d_in, const int* in_sizes, int n_in,
                              void* d_out, int out_size)
{
    const float* queries    = (const float*)d_in[0];
    const float* write_keys = (const float*)d_in[1];
    const float* write_vals = (const float*)d_in[2];
    const float* mem_keys   = (const float*)d_in[3];
    const float* mem_values = (const float*)d_in[4];
    const float* Wq         = (const float*)d_in[5];
    const float* bq         = (const float*)d_in[6];
    const float* Wvp        = (const float*)d_in[7];
    const float* bvp        = (const float*)d_in[8];
    const float* Wg         = (const float*)d_in[9];
    const float* bg         = (const float*)d_in[10];

    float* out_read = (float*)d_out;
    float* out_k    = out_read + (size_t)RB * KD_;
    float* out_v    = out_k    + (size_t)MEMN * KD_;

    void *pA, *pBV, *pRsum, *pIdx, *pPk;
    void *pQI16, *pQ16, *pP16, *pRV16, *pMK16, *pMVT16, *pWqT16, *pWvpT16;
    void *pKNh, *pKNl, *pMNh, *pMNl, *pWgTh, *pWgTl, *pWgBh, *pWgBl, *pWB16, *pGAh, *pGAl;
    cudaGetSymbolAddress(&pA, g_A);         cudaGetSymbolAddress(&pBV, g_BV);
    cudaGetSymbolAddress(&pRsum, g_rsum);
    cudaGetSymbolAddress(&pIdx, g_idx);     cudaGetSymbolAddress(&pPk, g_pk);
    cudaGetSymbolAddress(&pQI16, g_QI16);   cudaGetSymbolAddress(&pQ16, g_Q16);
    cudaGetSymbolAddress(&pP16, g_P16);     cudaGetSymbolAddress(&pRV16, g_RV16);
    cudaGetSymbolAddress(&pMK16, g_MK16);   cudaGetSymbolAddress(&pMVT16, g_MVT16);
    cudaGetSymbolAddress(&pWqT16, g_WqT16); cudaGetSymbolAddress(&pWvpT16, g_WvpT16);
    cudaGetSymbolAddress(&pKNh, g_KNh);     cudaGetSymbolAddress(&pKNl, g_KNl);
    cudaGetSymbolAddress(&pMNh, g_MNh);     cudaGetSymbolAddress(&pMNl, g_MNl);
    cudaGetSymbolAddress(&pWgTh, g_WgTh);   cudaGetSymbolAddress(&pWgTl, g_WgTl);
    cudaGetSymbolAddress(&pWgBh, g_WgBh);   cudaGetSymbolAddress(&pWgBl, g_WgBl);
    cudaGetSymbolAddress(&pWB16, g_WB16);
    cudaGetSymbolAddress(&pGAh, g_GAh);     cudaGetSymbolAddress(&pGAl, g_GAl);

    constexpr int DYN1_256 = 2 * (256 + TN) * ROWB1;
    constexpr int DYN1_128 = 2 * (128 + TN) * ROWB1;
    cudaFuncSetAttribute(bgemm3<3>,   cudaFuncAttributeMaxDynamicSharedMemorySize, DYN3);
    cudaFuncSetAttribute(bgemm3s,     cudaFuncAttributeMaxDynamicSharedMemorySize, DYNS);
    cudaFuncSetAttribute(hgemm1<5,4>, cudaFuncAttributeMaxDynamicSharedMemorySize, DYN1_256);
    cudaFuncSetAttribute(hgemm1<1,4>, cudaFuncAttributeMaxDynamicSharedMemorySize, DYN1_256);
    cudaFuncSetAttribute(hgemm1<2,4>, cudaFuncAttributeMaxDynamicSharedMemorySize, DYN1_256);
    cudaFuncSetAttribute(hgemm1<0,2>, cudaFuncAttributeMaxDynamicSharedMemorySize, DYN1_128);

    static cudaStream_t s2 = nullptr;
    static cudaEvent_t eF0 = nullptr, ePrep = nullptr, eMVT = nullptr, eW = nullptr, eJ = nullptr;
    if (s2 == nullptr) {
        cudaStreamCreateWithFlags(&s2, cudaStreamNonBlocking);
        cudaEventCreateWithFlags(&eF0,   cudaEventDisableTiming);
        cudaEventCreateWithFlags(&ePrep, cudaEventDisableTiming);
        cudaEventCreateWithFlags(&eMVT,  cudaEventDisableTiming);
        cudaEventCreateWithFlags(&eW,    cudaEventDisableTiming);
        cudaEventCreateWithFlags(&eJ,    cudaEventDisableTiming);
    }

    const float qscale = 0.044194173824159216f;  // 1/sqrt(512)/TEMP

    // ---- fork ----
    cudaEventRecord(eF0, 0);
    cudaStreamWaitEvent(s2, eF0, 0);

    // ---- s2: shared prep first (gates scores), then write path ----
    cudaMemsetAsync(pPk, 0, BWN * sizeof(unsigned long long), s2);
    cudaMemsetAsync(pRsum, 0, RQ * sizeof(float), s2);
    mem_prep<<<MEMN, 256, 0, s2>>>(mem_keys, (bf16*)pMNh, (bf16*)pMNl, (__half*)pMK16);
    wk_prep<<<BWN, 256, 0, s2>>>(write_keys, (bf16*)pKNh, (bf16*)pKNl, (bf16*)pGAh, (bf16*)pGAl);
    cudaEventRecord(ePrep, s2);                 // MK16 + rsum ready (scores gate)
    transpose_half<<<dim3(KD_/32, MEMN/32), 256, 0, s2>>>(mem_values, (__half*)pMVT16, MEMN, KD_);
    cudaEventRecord(eMVT, s2);                  // MVT16 ready (AV gate)
    transpose_split<<<dim3(KD_/32, KD_/32), 256, 0, s2>>>(Wg, (bf16*)pWgTh, (bf16*)pWgTl,
                                                          nullptr, KD_, KD_);
    transpose_split<<<dim3(KD_/32, KD_/32), 256, 0, s2>>>(Wg + (size_t)KD_ * KD_,
                                                          (bf16*)pWgBh, (bf16*)pWgBl,
                                                          (bf16*)pWB16, KD_, KD_);
    transpose_half<<<dim3(KD_/32, (HH*KD_)/32), 256, 0, s2>>>(Wvp, (__half*)pWvpT16, HH*KD_, KD_);
    cudaEventRecord(eW, s2);                    // WvpT16 ready (outproj gate)
    cudaMemcpyAsync(out_k, mem_keys,   (size_t)MEMN * KD_ * sizeof(float),
                    cudaMemcpyDeviceToDevice, s2);
    cudaMemcpyAsync(out_v, mem_values, (size_t)MEMN * KD_ * sizeof(float),
                    cudaMemcpyDeviceToDevice, s2);
    // sim (tensor path) + gate + chain — overlaps read-path GEMMs
    bgemm3<3><<<dim3(MEMN/TN, BWN/TM3), 256, DYN3, s2>>>(
        (bf16*)pKNh, (bf16*)pKNl, (bf16*)pMNh, (bf16*)pMNl,
        nullptr, nullptr, (unsigned long long*)pPk, BWN, MEMN, KD_, 1.0f);
    gather_unpack<<<BWN, 256, 0, s2>>>((unsigned long long*)pPk, mem_values, (int*)pIdx,
                                       (bf16*)pGAh, (bf16*)pGAl);
    bgemm3s<<<dim3(KD_/TNS, (2*BWN)/TMS), 128, DYNS, s2>>>(
        (bf16*)pGAh, (bf16*)pGAl,
        (bf16*)pWgTh, (bf16*)pWgTl, (bf16*)pWgBh, (bf16*)pWgBl,
        bg, (float*)pA, (float*)pBV);
    chain_update<<<MEMN, 256, 0, s2>>>(write_keys, write_vals, (const uint32_t*)pWB16,
                                       (float*)pA, (float*)pBV,
                                       (int*)pIdx, mem_keys, mem_values, out_k, out_v);
    cudaEventRecord(eJ, s2);

    // ---- main: fused single-launch prologue, then read path ----
    prologue_fused<<<CVT_BLKS + 2048, 256>>>(queries, (__half*)pQI16, Wq, (__half*)pWqT16);
    hgemm1<1,4><<<dim3((HH*KD_)/TN, RB/256), 256, DYN1_256>>>(
        (__half*)pQI16, (__half*)pWqT16, bq, nullptr, (__half*)pQ16,
        nullptr, nullptr, RB, HH*KD_, KD_, qscale);
    cudaStreamWaitEvent(0, ePrep, 0);
    hgemm1<5,4><<<dim3(MEMN/TN, RQ/256), 256, DYN1_256>>>(
        (__half*)pQ16, (__half*)pMK16, nullptr, nullptr, (__half*)pP16,
        nullptr, (float*)pRsum, RQ, MEMN, KD_, 1.0f);
    cudaStreamWaitEvent(0, eMVT, 0);
    hgemm1<2,4><<<dim3(KD_/TN, RQ/256), 256, DYN1_256>>>(
        (__half*)pP16, (__half*)pMVT16, nullptr, nullptr, (__half*)pRV16,
        (float*)pRsum, nullptr, RQ, KD_, MEMN, 1.0f);
    cudaStreamWaitEvent(0, eW, 0);
    hgemm1<0,2><<<dim3(KD_/TN, RB/128), 128, DYN1_128>>>(
        (__half*)pRV16, (__half*)pWvpT16, bvp, out_read, nullptr,
        nullptr, nullptr, RB, KD_, HH*KD_, 1.0f);

    // ---- join ----
    cudaStreamWaitEvent(0, eJ, 0);
}

// round 16
// speedup vs baseline: 1.0018x; 1.0018x over previous
#include <cuda_runtime.h>
#include <cuda_bf16.h>
#include <cuda_fp16.h>
#include <math.h>
#include <stdint.h>

#define BB   4
#define NN_  1024
#define KD_  512
#define HH   8
#define MEMN 4096
#define BWN  1024
#define RQ   (BB*HH*NN_)
#define RB   (BB*NN_)

typedef __nv_bfloat16 bf16;

// ---------------- scratch ----------------
__device__ float  g_A  [(size_t)BWN * KD_];          // wk@WgTop + bg
__device__ float  g_BV [(size_t)BWN * KD_];          // V0[idx]@WgBot
__device__ float  g_rsum[RQ];                        // softmax row sums
__device__ int    g_idx[BWN];
__device__ unsigned long long g_pk[BWN];             // packed (val,idx) argmax
__device__ __half g_QI16[(size_t)RB * KD_];
__device__ __half g_Q16[(size_t)RQ * KD_];
__device__ __half g_P16[(size_t)RQ * MEMN];          // exp(scores) fp16
__device__ __half g_RV16[(size_t)RB * (HH*KD_)];
__device__ __half g_MK16[(size_t)MEMN * KD_];
__device__ __half g_MVT16[(size_t)KD_ * MEMN];
__device__ __half g_WqT16[(size_t)(HH*KD_) * KD_];
__device__ __half g_WvpT16[(size_t)KD_ * (HH*KD_)];
__device__ bf16 g_KNh[(size_t)BWN * KD_],  g_KNl[(size_t)BWN * KD_];
__device__ bf16 g_MNh[(size_t)MEMN * KD_], g_MNl[(size_t)MEMN * KD_];
__device__ bf16 g_WgTh[(size_t)KD_ * KD_], g_WgTl[(size_t)KD_ * KD_];
__device__ bf16 g_WgBh[(size_t)KD_ * KD_], g_WgBl[(size_t)KD_ * KD_];
__device__ bf16 g_WB16[(size_t)KD_ * KD_];           // WgBot row-major bf16 (chain matvec)
__device__ bf16 g_GAh[(size_t)2*BWN * KD_], g_GAl[(size_t)2*BWN * KD_];  // [wk rows | V0[idx] rows]

// ---------------- helpers ----------------
__device__ __forceinline__ uint32_t smem_to_u32(const void* p) {
    uint32_t a;
    asm("{ .reg .u64 t; cvta.to.shared.u64 t, %1; cvt.u32.u64 %0, t; }" : "=r"(a) : "l"(p));
    return a;
}
__device__ __forceinline__ void ldsm4(uint32_t* r, uint32_t addr) {
    asm volatile("ldmatrix.sync.aligned.m8n8.x4.shared.b16 {%0,%1,%2,%3}, [%4];"
                 : "=r"(r[0]), "=r"(r[1]), "=r"(r[2]), "=r"(r[3]) : "r"(addr));
}
__device__ __forceinline__ void mma_bf(float* c, const uint32_t* a, const uint32_t* b) {
    asm volatile(
        "mma.sync.aligned.m16n8k16.row.col.f32.bf16.bf16.f32 "
        "{%0,%1,%2,%3}, {%4,%5,%6,%7}, {%8,%9}, {%0,%1,%2,%3};"
        : "+f"(c[0]), "+f"(c[1]), "+f"(c[2]), "+f"(c[3])
        : "r"(a[0]), "r"(a[1]), "r"(a[2]), "r"(a[3]), "r"(b[0]), "r"(b[1]));
}
__device__ __forceinline__ void mma_fp(float* c, const uint32_t* a, const uint32_t* b) {
    asm volatile(
        "mma.sync.aligned.m16n8k16.row.col.f32.f16.f16.f32 "
        "{%0,%1,%2,%3}, {%4,%5,%6,%7}, {%8,%9}, {%0,%1,%2,%3};"
        : "+f"(c[0]), "+f"(c[1]), "+f"(c[2]), "+f"(c[3])
        : "r"(a[0]), "r"(a[1]), "r"(a[2]), "r"(a[3]), "r"(b[0]), "r"(b[1]));
}
__device__ __forceinline__ void cp16(uint32_t dst, const void* src) {
    asm volatile("cp.async.cg.shared.global [%0], [%1], 16;" :: "r"(dst), "l"(src));
}
#define CP_COMMIT() asm volatile("cp.async.commit_group;" ::: "memory")
#define CP_WAIT1()  asm volatile("cp.async.wait_group 1;" ::: "memory")

__device__ __forceinline__ void splitpack(float x, float y, uint32_t& h, uint32_t& l) {
    bf16 hx = __float2bfloat16(x), hy = __float2bfloat16(y);
    float rx = x - __bfloat162float(hx), ry = y - __bfloat162float(hy);
    bf16 lx = __float2bfloat16(rx), ly = __float2bfloat16(ry);
    h = (uint32_t)__bfloat16_as_ushort(hx) | ((uint32_t)__bfloat16_as_ushort(hy) << 16);
    l = (uint32_t)__bfloat16_as_ushort(lx) | ((uint32_t)__bfloat16_as_ushort(ly) << 16);
}
__device__ __forceinline__ unsigned long long packmax(float v, int col) {
    uint32_t b = __float_as_uint(v);
    b = (b & 0x80000000u) ? ~b : (b | 0x80000000u);
    return ((unsigned long long)b << 32) | (unsigned long long)(0xFFFFFFFFu - (uint32_t)col);
}
__device__ __forceinline__ float2 bf2_to_f2(uint32_t u) {
    float2 r;
    r.x = __uint_as_float(u << 16);
    r.y = __uint_as_float(u & 0xFFFF0000u);
    return r;
}

#define TN 128
#define ROWB 144    // KC=32 bf16 hi|lo row
#define ROWB1 272   // KC=128 fp16 row
#define KC3 32

template<int MODE>
__device__ __forceinline__ size_t dst_of(int r, int c, int N) {
    if (MODE == 0 || MODE == 5) return (size_t)r * N + c;
    if (MODE == 1) {
        const int b_ = r >> 10, n_ = r & 1023, h_ = c >> 9, d_ = c & 511;
        return ((size_t)((b_ * 8 + h_) * 1024 + n_) << 9) + d_;
    }
    const int b_ = r >> 13, h_ = (r >> 10) & 7, n_ = r & 1023;
    return ((size_t)(b_ * 1024 + n_) << 12) + ((size_t)h_ << 9) + c;
}

// ================= 3-term split-bf16 GEMM, TM=256 (MODE 3: fused row-argmax) =================
#define TM3 256
#define STAGE3 ((TM3 + TN) * ROWB)
#define DYN3 (2 * STAGE3)

template<int MODE>
__global__ void __launch_bounds__(256, 1)
bgemm3(const bf16* __restrict__ Ah, const bf16* __restrict__ Al,
       const bf16* __restrict__ Bh, const bf16* __restrict__ Bl,
       const float* __restrict__ bias, float* __restrict__ C,
       unsigned long long* __restrict__ Packed,
       int M, int N, int K, float scale)
{
    extern __shared__ char sm[];
    const uint32_t smem_u = smem_to_u32(sm);
    const int tid = threadIdx.x;
    const int lane = tid & 31, wid = tid >> 5;
    const int bm = blockIdx.y * TM3, bn = blockIdx.x * TN;
    const int wm = (wid >> 1) * 64, wn = (wid & 1) * 64;

    float acc[4][8][4];
#pragma unroll
    for (int i = 0; i < 4; i++)
#pragma unroll
        for (int j = 0; j < 8; j++)
#pragma unroll
            for (int k = 0; k < 4; k++) acc[i][j][k] = 0.0f;

    const int NC = K / KC3;

    auto load_chunk = [&](int c, int st) {
        const int k0 = c * KC3;
        const uint32_t sb = smem_u + st * STAGE3;
#pragma unroll
        for (int u = 0; u < 3; u++) {
            const int unit = tid + u * 256;
            const int r = (unit & 511) >> 1, pl = unit & 1;
            const bf16* src;
            uint32_t dst;
            if (unit < 512) {
                src = (pl ? Al : Ah) + (size_t)(bm + r) * K + k0;
                dst = sb + r * ROWB + pl * 64;
            } else {
                src = (pl ? Bl : Bh) + (size_t)(bn + r) * K + k0;
                dst = sb + (TM3 + r) * ROWB + pl * 64;
            }
#pragma unroll
            for (int i = 0; i < 4; i++) cp16(dst + i * 16, src + i * 8);
        }
    };

    load_chunk(0, 0); CP_COMMIT();
    load_chunk(1, 1); CP_COMMIT();

    const int mr = lane & 7, msel = lane >> 3;
    const int aro = ((msel & 1) << 3) + mr;
    const int aco = (msel >> 1) << 3;
    const int bro = ((msel >> 1) << 3) + mr;
    const int bco = (msel & 1) << 3;

    for (int c = 0; c < NC; c++) {
        CP_WAIT1();
        __syncthreads();
        const uint32_t base = smem_u + (c & 1) * STAGE3;
#pragma unroll
        for (int ks = 0; ks < 2; ks++) {
            uint32_t ah[4][4], al[4][4], bh[8][2], bl[8][2];
            const int colA = (ks * 16 + aco) * 2;
            const int colB = (ks * 16 + bco) * 2;
#pragma unroll
            for (int mi = 0; mi < 4; mi++) {
                const uint32_t ad = base + (wm + mi * 16 + aro) * ROWB + colA;
                ldsm4(ah[mi], ad);
                ldsm4(al[mi], ad + 64);
            }
#pragma unroll
            for (int g = 0; g < 4; g++) {
                const uint32_t bd = base + (TM3 + wn + g * 16 + bro) * ROWB + colB;
                uint32_t t[4];
                ldsm4(t, bd);
                bh[2*g][0] = t[0]; bh[2*g][1] = t[1];
                bh[2*g+1][0] = t[2]; bh[2*g+1][1] = t[3];
                ldsm4(t, bd + 64);
                bl[2*g][0] = t[0]; bl[2*g][1] = t[1];
                bl[2*g+1][0] = t[2]; bl[2*g+1][1] = t[3];
            }
#pragma unroll
            for (int mi = 0; mi < 4; mi++)
#pragma unroll
                for (int nb = 0; nb < 8; nb++) {
                    mma_bf(acc[mi][nb], ah[mi], bh[nb]);
                    mma_bf(acc[mi][nb], ah[mi], bl[nb]);
                    mma_bf(acc[mi][nb], al[mi], bh[nb]);
                }
        }
        __syncthreads();
        if (c + 2 < NC) load_chunk(c + 2, c & 1);
        CP_COMMIT();
    }

    const int group = lane >> 2, tig = lane & 3;
    if (MODE == 3) {
#pragma unroll
        for (int mi = 0; mi < 4; mi++) {
#pragma unroll
            for (int half = 0; half < 2; half++) {
                const int row = bm + wm + mi * 16 + group + half * 8;
                float bv = -1e30f; int bc = 0;
#pragma unroll
                for (int nb = 0; nb < 8; nb++) {
                    const int col = bn + wn + nb * 8 + tig * 2;
                    const float v0 = acc[mi][nb][half * 2 + 0];
                    const float v1 = acc[mi][nb][half * 2 + 1];
                    if (v0 > bv) { bv = v0; bc = col; }
                    if (v1 > bv) { bv = v1; bc = col + 1; }
                }
#pragma unroll
                for (int m = 1; m <= 2; m <<= 1) {
                    float ov = __shfl_xor_sync(0xffffffffu, bv, m);
                    int   oc = __shfl_xor_sync(0xffffffffu, bc, m);
                    if (ov > bv || (ov == bv && oc < bc)) { bv = ov; bc = oc; }
                }
                if (tig == 0) atomicMax(Packed + row, packmax(bv, bc));
            }
        }
    } else {
#pragma unroll
        for (int mi = 0; mi < 4; mi++) {
            const int r_lo = bm + wm + mi * 16 + group;
#pragma unroll
            for (int nb = 0; nb < 8; nb++) {
                const int col = bn + wn + nb * 8 + tig * 2;
                float b0 = 0.0f, b1 = 0.0f;
                if (bias) { b0 = bias[col]; b1 = bias[col + 1]; }
                *reinterpret_cast<float2*>(&C[(size_t)r_lo * N + col]) =
                    make_float2((acc[mi][nb][0] + b0) * scale, (acc[mi][nb][1] + b1) * scale);
                *reinterpret_cast<float2*>(&C[(size_t)(r_lo + 8) * N + col]) =
                    make_float2((acc[mi][nb][2] + b0) * scale, (acc[mi][nb][3] + b1) * scale);
            }
        }
    }
}

// ====== small-tile 3-term gate GEMM: M=2048 (rows<1024: WgT+bias->outA; else WgB->outBV) ======
#define TMS 64
#define TNS 64
#define STAGES ((TMS + TNS) * ROWB)
#define DYNS (2 * STAGES)

__global__ void __launch_bounds__(128, 1)
bgemm3s(const bf16* __restrict__ Ah, const bf16* __restrict__ Al,
        const bf16* __restrict__ B1h, const bf16* __restrict__ B1l,
        const bf16* __restrict__ B2h, const bf16* __restrict__ B2l,
        const float* __restrict__ bias, float* __restrict__ outA, float* __restrict__ outBV)
{
    constexpr int K = KD_, N = KD_;
    extern __shared__ char sm[];
    const uint32_t smem_u = smem_to_u32(sm);
    const int tid = threadIdx.x;
    const int lane = tid & 31, wid = tid >> 5;
    const int bm = blockIdx.y * TMS, bn = blockIdx.x * TNS;
    const bool second = bm >= BWN;
    const bf16* Bh = second ? B2h : B1h;
    const bf16* Bl = second ? B2l : B1l;
    float* out = second ? outBV : outA;
    const int rowbase = second ? bm - BWN : bm;
    const int wm = (wid >> 1) * 32, wn = (wid & 1) * 32;

    float acc[2][4][4];
#pragma unroll
    for (int i = 0; i < 2; i++)
#pragma unroll
        for (int j = 0; j < 4; j++)
#pragma unroll
            for (int k = 0; k < 4; k++) acc[i][j][k] = 0.0f;

    const int NC = K / KC3;

    auto load_chunk = [&](int c, int st) {
        const int k0 = c * KC3;
        const uint32_t sb = smem_u + st * STAGES;
#pragma unroll
        for (int u = 0; u < 2; u++) {
            const int unit = tid + u * 128;
            const int r = (unit & 127) >> 1, pl = unit & 1;
            const bf16* src;
            uint32_t dst;
            if (unit < 128) {
                src = (pl ? Al : Ah) + (size_t)(bm + r) * K + k0;
                dst = sb + r * ROWB + pl * 64;
            } else {
                src = (pl ? Bl : Bh) + (size_t)(bn + r) * K + k0;
                dst = sb + (TMS + r) * ROWB + pl * 64;
            }
#pragma unroll
            for (int i = 0; i < 4; i++) cp16(dst + i * 16, src + i * 8);
        }
    };

    load_chunk(0, 0); CP_COMMIT();
    load_chunk(1, 1); CP_COMMIT();

    const int mr = lane & 7, msel = lane >> 3;
    const int aro = ((msel & 1) << 3) + mr;
    const int aco = (msel >> 1) << 3;
    const int bro = ((msel >> 1) << 3) + mr;
    const int bco = (msel & 1) << 3;

    for (int c = 0; c < NC; c++) {
        CP_WAIT1();
        __syncthreads();
        const uint32_t base = smem_u + (c & 1) * STAGES;
#pragma unroll
        for (int ks = 0; ks < 2; ks++) {
            uint32_t ah[2][4], al[2][4], bh[4][2], bl[4][2];
            const int colA = (ks * 16 + aco) * 2;
            const int colB = (ks * 16 + bco) * 2;
#pragma unroll
            for (int mi = 0; mi < 2; mi++) {
                const uint32_t ad = base + (wm + mi * 16 + aro) * ROWB + colA;
                ldsm4(ah[mi], ad);
                ldsm4(al[mi], ad + 64);
            }
#pragma unroll
            for (int g = 0; g < 2; g++) {
                const uint32_t bd = base + (TMS + wn + g * 16 + bro) * ROWB + colB;
                uint32_t t[4];
                ldsm4(t, bd);
                bh[2*g][0] = t[0]; bh[2*g][1] = t[1];
                bh[2*g+1][0] = t[2]; bh[2*g+1][1] = t[3];
                ldsm4(t, bd + 64);
                bl[2*g][0] = t[0]; bl[2*g][1] = t[1];
                bl[2*g+1][0] = t[2]; bl[2*g+1][1] = t[3];
            }
#pragma unroll
            for (int mi = 0; mi < 2; mi++)
#pragma unroll
                for (int nb = 0; nb < 4; nb++) {
                    mma_bf(acc[mi][nb], ah[mi], bh[nb]);
                    mma_bf(acc[mi][nb], ah[mi], bl[nb]);
                    mma_bf(acc[mi][nb], al[mi], bh[nb]);
                }
        }
        __syncthreads();
        if (c + 2 < NC) load_chunk(c + 2, c & 1);
        CP_COMMIT();
    }

    const int group = lane >> 2, tig = lane & 3;
#pragma unroll
    for (int mi = 0; mi < 2; mi++) {
        const int r_lo = rowbase + wm + mi * 16 + group;
#pragma unroll
        for (int nb = 0; nb < 4; nb++) {
            const int col = bn + wn + nb * 8 + tig * 2;
            float b0 = 0.0f, b1 = 0.0f;
            if (!second) { b0 = bias[col]; b1 = bias[col + 1]; }
            *reinterpret_cast<float2*>(&out[(size_t)r_lo * N + col]) =
                make_float2(acc[mi][nb][0] + b0, acc[mi][nb][1] + b1);
            *reinterpret_cast<float2*>(&out[(size_t)(r_lo + 8) * N + col]) =
                make_float2(acc[mi][nb][2] + b0, acc[mi][nb][3] + b1);
        }
    }
}

// ================= single-term fp16 GEMM (KC=128), TM = WM*64 =================
#define KC1 128

template<int MODE, int WM>
__global__ void __launch_bounds__(WM*64, 1)
hgemm1(const __half* __restrict__ A, const __half* __restrict__ B,
       const float* __restrict__ bias,
       float* __restrict__ C, __half* __restrict__ C16,
       const float* __restrict__ rsum, float* __restrict__ rsumo,
       int M, int N, int K, float scale)
{
    constexpr int TMv = WM * 64;
    constexpr int NT  = WM * 64;
    constexpr int STAGE = (TMv + TN) * ROWB1;
    extern __shared__ char sm[];
    const uint32_t smem_u = smem_to_u32(sm);
    const int tid = threadIdx.x;
    const int lane = tid & 31, wid = tid >> 5;
    const int bm = blockIdx.y * TMv, bn = blockIdx.x * TN;
    const int wm = (wid >> 1) * 64, wn = (wid & 1) * 64;

    float acc[4][8][4];
#pragma unroll
    for (int i = 0; i < 4; i++)
#pragma unroll
        for (int j = 0; j < 8; j++)
#pragma unroll
            for (int k = 0; k < 4; k++) acc[i][j][k] = 0.0f;

    const int NC = K / KC1;

    auto load_chunk = [&](int c, int st) {
        const int k0 = c * KC1;
        const uint32_t sb = smem_u + st * STAGE;
#pragma unroll
        for (int u = tid; u < (TMv + TN) * 16; u += NT) {
            const int r = u >> 4, seg = u & 15;
            const __half* src = (r < TMv)
                ? A + (size_t)(bm + r) * K + k0 + seg * 8
                : B + (size_t)(bn + (r - TMv)) * K + k0 + seg * 8;
            cp16(sb + r * ROWB1 + seg * 16, src);
        }
    };

    load_chunk(0, 0); CP_COMMIT();
    load_chunk(1, 1); CP_COMMIT();

    const int mr = lane & 7, msel = lane >> 3;
    const int aro = ((msel & 1) << 3) + mr;
    const int aco = (msel >> 1) << 3;
    const int bro = ((msel >> 1) << 3) + mr;
    const int bco = (msel & 1) << 3;

    for (int c = 0; c < NC; c++) {
        CP_WAIT1();
        __syncthreads();
        const uint32_t base = smem_u + (c & 1) * STAGE;
#pragma unroll
        for (int ks = 0; ks < 8; ks++) {
            uint32_t ah[4][4], bh[8][2];
            const int colA = (ks * 16 + aco) * 2;
            const int colB = (ks * 16 + bco) * 2;
#pragma unroll
            for (int mi = 0; mi < 4; mi++)
                ldsm4(ah[mi], base + (wm + mi * 16 + aro) * ROWB1 + colA);
#pragma unroll
            for (int g = 0; g < 4; g++) {
                uint32_t t[4];
                ldsm4(t, base + (TMv + wn + g * 16 + bro) * ROWB1 + colB);
                bh[2*g][0] = t[0]; bh[2*g][1] = t[1];
                bh[2*g+1][0] = t[2]; bh[2*g+1][1] = t[3];
            }
#pragma unroll
            for (int mi = 0; mi < 4; mi++)
#pragma unroll
                for (int nb = 0; nb < 8; nb++)
                    mma_fp(acc[mi][nb], ah[mi], bh[nb]);
        }
        __syncthreads();
        if (c + 2 < NC) load_chunk(c + 2, c & 1);
        CP_COMMIT();
    }

    const int group = lane >> 2, tig = lane & 3;
    if (MODE == 5) {
#pragma unroll
        for (int mi = 0; mi < 4; mi++) {
            const int r_lo = bm + wm + mi * 16 + group;
            float rs0 = 0.0f, rs1 = 0.0f;
#pragma unroll
            for (int nb = 0; nb < 8; nb++) {
                const int col = bn + wn + nb * 8 + tig * 2;
                float e00 = __expf(acc[mi][nb][0]);
                float e01 = __expf(acc[mi][nb][1]);
                float e10 = __expf(acc[mi][nb][2]);
                float e11 = __expf(acc[mi][nb][3]);
                rs0 += e00 + e01;
                rs1 += e10 + e11;
                *reinterpret_cast<__half2*>(&C16[(size_t)r_lo * N + col]) = __floats2half2_rn(e00, e01);
                *reinterpret_cast<__half2*>(&C16[(size_t)(r_lo + 8) * N + col]) = __floats2half2_rn(e10, e11);
            }
            rs0 += __shfl_xor_sync(0xffffffffu, rs0, 1);
            rs0 += __shfl_xor_sync(0xffffffffu, rs0, 2);
            rs1 += __shfl_xor_sync(0xffffffffu, rs1, 1);
            rs1 += __shfl_xor_sync(0xffffffffu, rs1, 2);
            if (tig == 0) {
                atomicAdd(rsumo + r_lo, rs0);
                atomicAdd(rsumo + r_lo + 8, rs1);
            }
        }
    } else {
#pragma unroll
        for (int mi = 0; mi < 4; mi++) {
            const int r_lo = bm + wm + mi * 16 + group;
            float s0 = scale, s1 = scale;
            if (MODE == 2) {
                s0 = scale / rsum[r_lo];
                s1 = scale / rsum[r_lo + 8];
            }
#pragma unroll
            for (int nb = 0; nb < 8; nb++) {
                const int col = bn + wn + nb * 8 + tig * 2;
                float b0 = 0.0f, b1 = 0.0f;
                if (bias) { b0 = bias[col]; b1 = bias[col + 1]; }
                float v00 = (acc[mi][nb][0] + b0) * s0;
                float v01 = (acc[mi][nb][1] + b1) * s0;
                float v10 = (acc[mi][nb][2] + b0) * s1;
                float v11 = (acc[mi][nb][3] + b1) * s1;
                if (MODE == 0) {
                    *reinterpret_cast<float2*>(&C[dst_of<0>(r_lo,     col, N)]) = make_float2(v00, v01);
                    *reinterpret_cast<float2*>(&C[dst_of<0>(r_lo + 8, col, N)]) = make_float2(v10, v11);
                } else {
                    *reinterpret_cast<__half2*>(&C16[dst_of<MODE>(r_lo,     col, N)]) = __floats2half2_rn(v00, v01);
                    *reinterpret_cast<__half2*>(&C16[dst_of<MODE>(r_lo + 8, col, N)]) = __floats2half2_rn(v10, v11);
                }
            }
        }
    }
}

// ---------------- prep / small kernels ----------------
__global__ void __launch_bounds__(256) transpose_split(const float* __restrict__ in,
                                                       bf16* __restrict__ oh, bf16* __restrict__ ol,
                                                       bf16* __restrict__ raw16,
                                                       int R, int C)
{
    __shared__ float t[32][33];
    const int c0 = blockIdx.x * 32, r0 = blockIdx.y * 32;
    const int x = threadIdx.x & 31, y = threadIdx.x >> 5;
#pragma unroll
    for (int i = 0; i < 32; i += 8) {
        float v = in[(size_t)(r0 + y + i) * C + c0 + x];
        t[y + i][x] = v;
        if (raw16) raw16[(size_t)(r0 + y + i) * C + c0 + x] = __float2bfloat16(v);
    }
    __syncthreads();
#pragma unroll
    for (int i = 0; i < 32; i += 8) {
        float v = t[x][y + i];
        bf16 h = __float2bfloat16(v);
        bf16 l = __float2bfloat16(v - __bfloat162float(h));
        const size_t d = (size_t)(c0 + y + i) * R + r0 + x;
        oh[d] = h; ol[d] = l;
    }
}

__global__ void __launch_bounds__(256) transpose_half(const float* __restrict__ in,
                                                      __half* __restrict__ out, int R, int C)
{
    __shared__ float t[32][33];
    const int c0 = blockIdx.x * 32, r0 = blockIdx.y * 32;
    const int x = threadIdx.x & 31, y = threadIdx.x >> 5;
#pragma unroll
    for (int i = 0; i < 32; i += 8) t[y + i][x] = in[(size_t)(r0 + y + i) * C + c0 + x];
    __syncthreads();
#pragma unroll
    for (int i = 0; i < 32; i += 8)
        out[(size_t)(c0 + y + i) * R + r0 + x] = __float2half(t[x][y + i]);
}

__global__ void __launch_bounds__(256) cvt_half(const float* __restrict__ in,
                                                __half* __restrict__ out, int n2)
{
    int i = (blockIdx.x * 256 + threadIdx.x) * 2;
    if (i < n2) {
        float2 v = *reinterpret_cast<const float2*>(&in[i]);
        *reinterpret_cast<__half2*>(&out[i]) = __floats2half2_rn(v.x, v.y);
    }
}

// mem_keys: one read -> normalized bf16 planes + raw fp16
__global__ void __launch_bounds__(256) mem_prep(const float* __restrict__ X,
                                                bf16* __restrict__ oh, bf16* __restrict__ ol,
                                                __half* __restrict__ o16)
{
    __shared__ float red[256];
    const int r = blockIdx.x, tid = threadIdx.x;
    const float* p = X + (size_t)r * KD_;
    float ss = 0.0f;
    for (int i = tid; i < KD_; i += 256) { float v = p[i]; ss += v * v; }
    red[tid] = ss; __syncthreads();
    for (int s = 128; s > 0; s >>= 1) { if (tid < s) red[tid] += red[tid + s]; __syncthreads(); }
    const float inv = 1.0f / fmaxf(sqrtf(red[0]), 1e-8f);
    const int i = tid * 2;
    float2 v = *reinterpret_cast<const float2*>(&p[i]);
    uint32_t h, l;
    splitpack(v.x * inv, v.y * inv, h, l);
    *reinterpret_cast<uint32_t*>(&oh[(size_t)r * KD_ + i]) = h;
    *reinterpret_cast<uint32_t*>(&ol[(size_t)r * KD_ + i]) = l;
    *reinterpret_cast<__half2*>(&o16[(size_t)r * KD_ + i]) = __floats2half2_rn(v.x, v.y);
}

// write_keys: one read -> normalized planes (sim) + raw planes (gate top half)
__global__ void __launch_bounds__(256) wk_prep(const float* __restrict__ X,
                                               bf16* __restrict__ nh, bf16* __restrict__ nl,
                                               bf16* __restrict__ gh, bf16* __restrict__ gl)
{
    __shared__ float red[256];
    const int r = blockIdx.x, tid = threadIdx.x;
    const float* p = X + (size_t)r * KD_;
    float ss = 0.0f;
    for (int i = tid; i < KD_; i += 256) { float v = p[i]; ss += v * v; }
    red[tid] = ss; __syncthreads();
    for (int s = 128; s > 0; s >>= 1) { if (tid < s) red[tid] += red[tid + s]; __syncthreads(); }
    const float inv = 1.0f / fmaxf(sqrtf(red[0]), 1e-8f);
    const int i = tid * 2;
    float2 v = *reinterpret_cast<const float2*>(&p[i]);
    uint32_t h, l;
    splitpack(v.x * inv, v.y * inv, h, l);
    *reinterpret_cast<uint32_t*>(&nh[(size_t)r * KD_ + i]) = h;
    *reinterpret_cast<uint32_t*>(&nl[(size_t)r * KD_ + i]) = l;
    splitpack(v.x, v.y, h, l);
    *reinterpret_cast<uint32_t*>(&gh[(size_t)r * KD_ + i]) = h;
    *reinterpret_cast<uint32_t*>(&gl[(size_t)r * KD_ + i]) = l;
}

__global__ void __launch_bounds__(256) gather_unpack(const unsigned long long* __restrict__ pk,
                                                     const float* __restrict__ mv,
                                                     int* __restrict__ idx,
                                                     bf16* __restrict__ gh, bf16* __restrict__ gl)
{
    const int t = blockIdx.x, tid = threadIdx.x;
    const unsigned long long v = pk[t];
    const int col = (int)(0xFFFFFFFFu - (uint32_t)(v & 0xFFFFFFFFu));
    if (tid == 0) idx[t] = col;
    const float* src = mv + (size_t)col * KD_;
    const int i = tid * 2;
    uint32_t h, l;
    splitpack(src[i], src[i + 1], h, l);
    *reinterpret_cast<uint32_t*>(&gh[(size_t)(BWN + t) * KD_ + i]) = h;
    *reinterpret_cast<uint32_t*>(&gl[(size_t)(BWN + t) * KD_ + i]) = l;
}

__global__ void __launch_bounds__(256) chain_update(
    const float* __restrict__ wk, const float* __restrict__ wv,
    const uint32_t* __restrict__ WB,
    const float* __restrict__ Aw,
    const float* __restrict__ BV,
    const int*   __restrict__ idx,
    const float* __restrict__ mk, const float* __restrict__ mv,
    float* __restrict__ outK, float* __restrict__ outV)
{
    __shared__ float sK[KD_], sV[KD_];
    __shared__ int   list[BWN];
    __shared__ int   cnt;
    const int s = blockIdx.x, tid = threadIdx.x;
    if (tid == 0) cnt = 0;
    __syncthreads();
    for (int t = tid; t < BWN; t += 256)
        if (idx[t] == s) { int p = atomicAdd(&cnt, 1); list[p] = t; }
    __syncthreads();
    const int n = cnt;
    if (n == 0) return;
    if (tid == 0) {
        for (int i = 1; i < n; i++) {
            int v = list[i], j = i - 1;
            while (j >= 0 && list[j] > v) { list[j + 1] = list[j]; j--; }
            list[j + 1] = v;
        }
    }
    for (int i = tid; i < KD_; i += 256) {
        sK[i] = mk[(size_t)s * KD_ + i];
        sV[i] = mv[(size_t)s * KD_ + i];
    }
    __syncthreads();
    const int j0 = tid * 2;
    for (int e = 0; e < n; e++) {
        const int t = list[e];
        float a0, a1;
        {
            float2 aw = *reinterpret_cast<const float2*>(&Aw[(size_t)t * KD_ + j0]);
            a0 = aw.x; a1 = aw.y;
        }
        if (e == 0) {
            float2 bv = *reinterpret_cast<const float2*>(&BV[(size_t)t * KD_ + j0]);
            a0 += bv.x; a1 += bv.y;
        } else {
#pragma unroll 8
            for (int r = 0; r < KD_; r++) {
                const float v = sV[r];
                float2 w = bf2_to_f2(WB[r * 256 + tid]);
                a0 += v * w.x;
                a1 += v * w.y;
            }
        }
        const float g0 = 1.0f / (1.0f + expf(-a0));
        const float g1 = 1.0f / (1.0f + expf(-a1));
        __syncthreads();
        float2 k2 = *reinterpret_cast<const float2*>(&wk[(size_t)t * KD_ + j0]);
        float2 v2 = *reinterpret_cast<const float2*>(&wv[(size_t)t * KD_ + j0]);
        sK[j0]     = g0 * k2.x + (1.0f - g0) * sK[j0];
        sK[j0 + 1] = g1 * k2.y + (1.0f - g1) * sK[j0 + 1];
        sV[j0]     = g0 * v2.x + (1.0f - g0) * sV[j0];
        sV[j0 + 1] = g1 * v2.y + (1.0f - g1) * sV[j0 + 1];
        __syncthreads();
    }
    for (int i = tid; i < KD_; i += 256) {
        outK[(size_t)s * KD_ + i] = sK[i];
        outV[(size_t)s * KD_ + i] = sV[i];
    }
}

// ---------------- launcher ----------------
extern "C" void kernel_launch(void* const* d_in, const int* in_sizes, int n_in,
                              void* d_out, int out_size)
{
    const float* queries    = (const float*)d_in[0];
    const float* write_keys = (const float*)d_in[1];
    const float* write_vals = (const float*)d_in[2];
    const float* mem_keys   = (const float*)d_in[3];
    const float* mem_values = (const float*)d_in[4];
    const float* Wq         = (const float*)d_in[5];
    const float* bq         = (const float*)d_in[6];
    const float* Wvp        = (const float*)d_in[7];
    const float* bvp        = (const float*)d_in[8];
    const float* Wg         = (const float*)d_in[9];
    const float* bg         = (const float*)d_in[10];

    float* out_read = (float*)d_out;
    float* out_k    = out_read + (size_t)RB * KD_;
    float* out_v    = out_k    + (size_t)MEMN * KD_;

    void *pA, *pBV, *pRsum, *pIdx, *pPk;
    void *pQI16, *pQ16, *pP16, *pRV16, *pMK16, *pMVT16, *pWqT16, *pWvpT16;
    void *pKNh, *pKNl, *pMNh, *pMNl, *pWgTh, *pWgTl, *pWgBh, *pWgBl, *pWB16, *pGAh, *pGAl;
    cudaGetSymbolAddress(&pA, g_A);         cudaGetSymbolAddress(&pBV, g_BV);
    cudaGetSymbolAddress(&pRsum, g_rsum);
    cudaGetSymbolAddress(&pIdx, g_idx);     cudaGetSymbolAddress(&pPk, g_pk);
    cudaGetSymbolAddress(&pQI16, g_QI16);   cudaGetSymbolAddress(&pQ16, g_Q16);
    cudaGetSymbolAddress(&pP16, g_P16);     cudaGetSymbolAddress(&pRV16, g_RV16);
    cudaGetSymbolAddress(&pMK16, g_MK16);   cudaGetSymbolAddress(&pMVT16, g_MVT16);
    cudaGetSymbolAddress(&pWqT16, g_WqT16); cudaGetSymbolAddress(&pWvpT16, g_WvpT16);
    cudaGetSymbolAddress(&pKNh, g_KNh);     cudaGetSymbolAddress(&pKNl, g_KNl);
    cudaGetSymbolAddress(&pMNh, g_MNh);     cudaGetSymbolAddress(&pMNl, g_MNl);
    cudaGetSymbolAddress(&pWgTh, g_WgTh);   cudaGetSymbolAddress(&pWgTl, g_WgTl);
    cudaGetSymbolAddress(&pWgBh, g_WgBh);   cudaGetSymbolAddress(&pWgBl, g_WgBl);
    cudaGetSymbolAddress(&pWB16, g_WB16);
    cudaGetSymbolAddress(&pGAh, g_GAh);     cudaGetSymbolAddress(&pGAl, g_GAl);

    constexpr int DYN1_256 = 2 * (256 + TN) * ROWB1;
    constexpr int DYN1_128 = 2 * (128 + TN) * ROWB1;
    cudaFuncSetAttribute(bgemm3<3>,   cudaFuncAttributeMaxDynamicSharedMemorySize, DYN3);
    cudaFuncSetAttribute(bgemm3s,     cudaFuncAttributeMaxDynamicSharedMemorySize, DYNS);
    cudaFuncSetAttribute(hgemm1<5,4>, cudaFuncAttributeMaxDynamicSharedMemorySize, DYN1_256);
    cudaFuncSetAttribute(hgemm1<1,4>, cudaFuncAttributeMaxDynamicSharedMemorySize, DYN1_256);
    cudaFuncSetAttribute(hgemm1<2,4>, cudaFuncAttributeMaxDynamicSharedMemorySize, DYN1_256);
    cudaFuncSetAttribute(hgemm1<0,2>, cudaFuncAttributeMaxDynamicSharedMemorySize, DYN1_128);

    static cudaStream_t s2 = nullptr;
    static cudaEvent_t eF0 = nullptr, ePrep = nullptr, eMVT = nullptr, eW = nullptr, eJ = nullptr;
    if (s2 == nullptr) {
        cudaStreamCreateWithFlags(&s2, cudaStreamNonBlocking);
        cudaEventCreateWithFlags(&eF0,   cudaEventDisableTiming);
        cudaEventCreateWithFlags(&ePrep, cudaEventDisableTiming);
        cudaEventCreateWithFlags(&eMVT,  cudaEventDisableTiming);
        cudaEventCreateWithFlags(&eW,    cudaEventDisableTiming);
        cudaEventCreateWithFlags(&eJ,    cudaEventDisableTiming);
    }

    const float qscale = 0.044194173824159216f;  // 1/sqrt(512)/TEMP

    // ---- fork ----
    cudaEventRecord(eF0, 0);
    cudaStreamWaitEvent(s2, eF0, 0);

    // ---- s2: shared prep first (gates scores), then write path ----
    cudaMemsetAsync(pPk, 0, BWN * sizeof(unsigned long long), s2);
    cudaMemsetAsync(pRsum, 0, RQ * sizeof(float), s2);
    mem_prep<<<MEMN, 256, 0, s2>>>(mem_keys, (bf16*)pMNh, (bf16*)pMNl, (__half*)pMK16);
    wk_prep<<<BWN, 256, 0, s2>>>(write_keys, (bf16*)pKNh, (bf16*)pKNl, (bf16*)pGAh, (bf16*)pGAl);
    cudaEventRecord(ePrep, s2);                 // MK16 + rsum ready (scores gate)
    transpose_half<<<dim3(KD_/32, MEMN/32), 256, 0, s2>>>(mem_values, (__half*)pMVT16, MEMN, KD_);
    cudaEventRecord(eMVT, s2);                  // MVT16 ready (AV gate)
    transpose_split<<<dim3(KD_/32, KD_/32), 256, 0, s2>>>(Wg, (bf16*)pWgTh, (bf16*)pWgTl,
                                                          nullptr, KD_, KD_);
    transpose_split<<<dim3(KD_/32, KD_/32), 256, 0, s2>>>(Wg + (size_t)KD_ * KD_,
                                                          (bf16*)pWgBh, (bf16*)pWgBl,
                                                          (bf16*)pWB16, KD_, KD_);
    transpose_half<<<dim3(KD_/32, (HH*KD_)/32), 256, 0, s2>>>(Wvp, (__half*)pWvpT16, HH*KD_, KD_);
    cudaEventRecord(eW, s2);                    // WvpT16 ready (outproj gate)
    cudaMemcpyAsync(out_k, mem_keys,   (size_t)MEMN * KD_ * sizeof(float),
                    cudaMemcpyDeviceToDevice, s2);
    cudaMemcpyAsync(out_v, mem_values, (size_t)MEMN * KD_ * sizeof(float),
                    cudaMemcpyDeviceToDevice, s2);
    // sim (tensor path) + gate + chain — overlaps read-path GEMMs
    bgemm3<3><<<dim3(MEMN/TN, BWN/TM3), 256, DYN3, s2>>>(
        (bf16*)pKNh, (bf16*)pKNl, (bf16*)pMNh, (bf16*)pMNl,
        nullptr, nullptr, (unsigned long long*)pPk, BWN, MEMN, KD_, 1.0f);
    gather_unpack<<<BWN, 256, 0, s2>>>((unsigned long long*)pPk, mem_values, (int*)pIdx,
                                       (bf16*)pGAh, (bf16*)pGAl);
    bgemm3s<<<dim3(KD_/TNS, (2*BWN)/TMS), 128, DYNS, s2>>>(
        (bf16*)pGAh, (bf16*)pGAl,
        (bf16*)pWgTh, (bf16*)pWgTl, (bf16*)pWgBh, (bf16*)pWgBl,
        bg, (float*)pA, (float*)pBV);
    chain_update<<<MEMN, 256, 0, s2>>>(write_keys, write_vals, (const uint32_t*)pWB16,
                                       (float*)pA, (float*)pBV,
                                       (int*)pIdx, mem_keys, mem_values, out_k, out_v);
    cudaEventRecord(eJ, s2);

    // ---- main: minimal prologue, then read path ----
    cvt_half<<<(RB*KD_/2 + 255)/256, 256>>>(queries, (__half*)pQI16, RB*KD_);
    transpose_half<<<dim3((HH*KD_)/32, KD_/32), 256>>>(Wq, (__half*)pWqT16, KD_, HH*KD_);
    hgemm1<1,4><<<dim3((HH*KD_)/TN, RB/256), 256, DYN1_256>>>(
        (__half*)pQI16, (__half*)pWqT16, bq, nullptr, (__half*)pQ16,
        nullptr, nullptr, RB, HH*KD_, KD_, qscale);
    cudaStreamWaitEvent(0, ePrep, 0);
    hgemm1<5,4><<<dim3(MEMN/TN, RQ/256), 256, DYN1_256>>>(
        (__half*)pQ16, (__half*)pMK16, nullptr, nullptr, (__half*)pP16,
        nullptr, (float*)pRsum, RQ, MEMN, KD_, 1.0f);
    cudaStreamWaitEvent(0, eMVT, 0);
    hgemm1<2,4><<<dim3(KD_/TN, RQ/256), 256, DYN1_256>>>(
        (__half*)pP16, (__half*)pMVT16, nullptr, nullptr, (__half*)pRV16,
        (float*)pRsum, nullptr, RQ, KD_, MEMN, 1.0f);
    cudaStreamWaitEvent(0, eW, 0);
    hgemm1<0,2><<<dim3(KD_/TN, RB/128), 128, DYN1_128>>>(
        (__half*)pRV16, (__half*)pWvpT16, bvp, out_read, nullptr,
        nullptr, nullptr, RB, KD_, HH*KD_, 1.0f);

    // ---- join ----
    cudaStreamWaitEvent(0, eJ, 0);
}